// round 15
// baseline (speedup 1.0000x reference)
#include <cuda_runtime.h>
#include <math.h>

// RepulsionLoss: points [4, 8192, 3] f32 -> scalar f32
// R15: ONE persistent kernel. R10's fusion regression was the per-thread
// __threadfence() (295k MEMBAR.GPU); R9's wrongness was __ldg on
// same-launch data. This version: tid0-only cumulative fence barrier
// (all-writes -> syncthreads -> tid0 fence.release -> arrive; PTX fences
// are cumulative so this publishes every thread's writes) + plain coherent
// loads in the knn phase. Build phases now run across all SMs; one launch
// envelope instead of two.

#define BATCH    4
#define NPTS     8192
#define TOTALPTS (BATCH * NPTS)
#define KNN      8
#define RADIUS   0.07f
#define H2_INV   (1.0f / (0.03f * 0.03f))
#define ALPHA    0.1f

#define GRIDC    18
#define NCELL    (GRIDC * GRIDC * GRIDC)   // 5832

#define QPB      32
#define NROW     9
#define KBLOCK   (QPB * NROW)              // 288 threads, 9 warps
#define KGRID    (BATCH * NPTS / QPB)      // 1024 blocks (all resident @ 7/SM)
#define MSTRIDE  (NROW * KNN + 1)          // 73: conflict-free columns

#define SCPT     21                        // scan cells/thread: 288*21 >= 5832

__device__ int    g_hist[BATCH][NCELL];    // ZERO invariant at launch entry
__device__ int    g_off [BATCH][NCELL + 1];
__device__ int    g_cur [BATCH][NCELL];
__device__ int2   g_rr  [BATCH][NCELL];
__device__ float4 g_sorted[BATCH][NPTS];
__device__ float        g_acc;             // restored to 0 by finalize
__device__ unsigned int g_tick;            // ditto
__device__ unsigned int g_bar_cnt;         // self-resetting
__device__ unsigned int g_bar_gen;         // monotonic across replays

static __device__ __forceinline__ int cell_coord(float v) {
    int c = (int)(v * (float)GRIDC);
    return c > GRIDC - 1 ? GRIDC - 1 : (c < 0 ? 0 : c);
}

static __device__ __forceinline__ void ins8(float best[KNN], float v) {
#pragma unroll
    for (int k = KNN - 1; k > 0; --k)
        best[k] = fminf(best[k], fmaxf(v, best[k - 1]));
    best[0] = fminf(best[0], v);
}

static __device__ __forceinline__ void bimerge(float m[KNN], const float* src) {
    float t[KNN];
#pragma unroll
    for (int i = 0; i < KNN; ++i)
        t[i] = fminf(m[i], src[KNN - 1 - i]);
#pragma unroll
    for (int i = 0; i < 4; ++i) {
        const float lo = fminf(t[i], t[i + 4]);
        const float hi = fmaxf(t[i], t[i + 4]);
        t[i] = lo; t[i + 4] = hi;
    }
#pragma unroll
    for (int h = 0; h < 8; h += 4)
#pragma unroll
        for (int i = 0; i < 2; ++i) {
            const float lo = fminf(t[h + i], t[h + i + 2]);
            const float hi = fmaxf(t[h + i], t[h + i + 2]);
            t[h + i] = lo; t[h + i + 2] = hi;
        }
#pragma unroll
    for (int i = 0; i < 8; i += 2) {
        const float lo = fminf(t[i], t[i + 1]);
        const float hi = fmaxf(t[i], t[i + 1]);
        t[i] = lo; t[i + 1] = hi;
    }
#pragma unroll
    for (int i = 0; i < KNN; ++i) m[i] = t[i];
}

// all-resident grid barrier, tid0-only fence (cumulative release/acquire)
static __device__ __forceinline__ void grid_barrier() {
    __syncthreads();                      // HB: all block writes -> tid0
    if (threadIdx.x == 0) {
        volatile unsigned int* genp = (volatile unsigned int*)&g_bar_gen;
        const unsigned int gen = *genp;   // read BEFORE arriving
        __threadfence();                  // cumulative release
        const unsigned int arrived = atomicAdd(&g_bar_cnt, 1u);
        if (arrived == (unsigned)KGRID - 1u) {
            g_bar_cnt = 0u;
            __threadfence();
            atomicAdd(&g_bar_gen, 1u);    // release the others
        } else {
            while (*genp == gen) { __nanosleep(64); }
        }
        __threadfence();                  // cumulative acquire
    }
    __syncthreads();                      // HB: tid0 -> all block threads
}

__global__ __launch_bounds__(KBLOCK, 7) void repulsion_kernel(
        const float* __restrict__ pts, float* __restrict__ out) {
    __shared__ float s_m[QPB][MSTRIDE];
    __shared__ int   s_wsum[NROW];

    const int tid  = threadIdx.x;
    const int lane = tid & 31;
    const int warp = tid >> 5;
    const int gtid = blockIdx.x * KBLOCK + tid;

    // ---- Phase A: histogram (one point/thread; coords stay in registers) --
    float px = 0.f, py = 0.f, pz = 0.f;
    int   pb = 0, pc = 0;
    if (gtid < TOTALPTS) {
        pb = gtid >> 13;
        px = __ldg(pts + 3 * (size_t)gtid + 0);
        py = __ldg(pts + 3 * (size_t)gtid + 1);
        pz = __ldg(pts + 3 * (size_t)gtid + 2);
        pc = (cell_coord(pz) * GRIDC + cell_coord(py)) * GRIDC + cell_coord(px);
        atomicAdd(&g_hist[pb][pc], 1);
    }
    grid_barrier();

    // ---- Phase B: scan + rowranges + cursors + hist re-zero (blocks 0..3) --
    if (blockIdx.x < BATCH) {
        const int b  = blockIdx.x;
        const int i0 = tid * SCPT;
        int v[SCPT];
        int sum = 0;
#pragma unroll
        for (int r = 0; r < SCPT; ++r) {
            const int i = i0 + r;
            const int x = (i < NCELL) ? g_hist[b][i] : 0;
            v[r] = x;
            sum += x;
        }
        int inc = sum;
#pragma unroll
        for (int off = 1; off < 32; off <<= 1) {
            const int n = __shfl_up_sync(0xffffffffu, inc, off);
            if (lane >= off) inc += n;
        }
        if (lane == 31) s_wsum[warp] = inc;
        __syncthreads();
        int wbase = 0;
        for (int w = 0; w < warp; ++w) wbase += s_wsum[w];
        int run = wbase + inc - sum;          // exclusive prefix
#pragma unroll
        for (int r = 0; r < SCPT; ++r) {
            const int i = i0 + r;
            if (i < NCELL) {
                g_off[b][i] = run;
                g_cur[b][i] = run;
                g_hist[b][i] = 0;             // restore zero-invariant
            }
            run += v[r];
        }
        if (tid == 0) g_off[b][NCELL] = NPTS; // sentinel
        __syncthreads();                      // g_off visible block-wide (same SM)

        for (int i = tid; i < NCELL; i += KBLOCK) {
            const int x  = i % GRIDC;
            const int rb = i - x;
            const int xs = g_off[b][rb + (x > 0 ? x - 1 : 0)];
            const int xe = g_off[b][rb + (x < GRIDC - 1 ? x + 1 : GRIDC - 1) + 1];
            g_rr[b][i] = make_int2(xs, xe);
        }
    }
    grid_barrier();

    // ---- Phase C: scatter (coords from registers; cursors via L2 atomics) --
    if (gtid < TOTALPTS) {
        const int pos = atomicAdd(&g_cur[pb][pc], 1);
        g_sorted[pb][pos] = make_float4(px, py, pz, 0.0f);
    }
    grid_barrier();

    // ---- Phase D: 9-way grid-KNN + loss (PLAIN loads: same-launch data) ----
    const int ri     = warp;
    const int qlocal = lane;

    const int blocks_per_batch = NPTS / QPB;   // 256
    const int b  = blockIdx.x / blocks_per_batch;
    const int qi = (blockIdx.x % blocks_per_batch) * QPB + qlocal;

    const float4 p = g_sorted[b][qi];
    const float qx = p.x, qy = p.y, qz = p.z;
    const int cx = cell_coord(qx);
    const int cy = cell_coord(qy);
    const int cz = cell_coord(qz);

    float best[KNN];
#pragma unroll
    for (int k = 0; k < KNN; ++k) best[k] = 3.0e38f;

    const int zz = cz - 1 + ri / 3;
    const int yy = cy - 1 + ri % 3;
    if ((unsigned)zz < GRIDC && (unsigned)yy < GRIDC) {
        const int2 r = g_rr[b][(zz * GRIDC + yy) * GRIDC + cx];
#pragma unroll 4
        for (int j = r.x; j < r.y; ++j) {
            const float4 c = g_sorted[b][j];
            const float dx = qx - c.x;
            const float dy = qy - c.y;
            const float dz = qz - c.z;
            const float d2 = fmaf(dx, dx, fmaf(dy, dy, dz * dz));
            ins8(best, d2);
        }
    }

#pragma unroll
    for (int k = 0; k < KNN; ++k) s_m[qlocal][ri * KNN + k] = best[k];
    __syncthreads();

    // merge tree: warp0 <- lists 1..3, warp4 <- lists 5..8 (parallel)
    float m[KNN];
    if (ri == 0 || ri == 4) {
#pragma unroll
        for (int k = 0; k < KNN; ++k) m[k] = best[k];
        const int first = (ri == 0) ? 1 : 5;
        const int last  = (ri == 0) ? 3 : 8;
        for (int r = first; r <= last; ++r)
            bimerge(m, &s_m[qlocal][r * KNN]);
        if (ri == 4) {
#pragma unroll
            for (int k = 0; k < KNN; ++k) s_m[qlocal][4 * KNN + k] = m[k];
        }
    }
    __syncthreads();

    if (ri == 0) {
        bimerge(m, &s_m[qlocal][4 * KNN]);

        float s = 0.0f;
#pragma unroll
        for (int k = 0; k < KNN; ++k) {
            const float d2 = m[k];
            const float dn = sqrtf(fmaxf(d2, 1e-12f));
            const float w  = __expf(-d2 * H2_INV);
            s = fmaf(RADIUS - dn, w, s);
        }
#pragma unroll
        for (int off = 16; off > 0; off >>= 1)
            s += __shfl_xor_sync(0xffffffffu, s, off);

        if (qlocal == 0) {
            atomicAdd(&g_acc, s);
            __threadfence();
            const unsigned t = atomicAdd(&g_tick, 1u);
            if (t == KGRID - 1) {
                __threadfence();
                const float total = atomicAdd(&g_acc, 0.0f);
                out[0] = ALPHA * total * (1.0f / (float)(BATCH * NPTS * KNN));
                g_acc = 0.0f;                  // restore for graph replay
                __threadfence();
                g_tick = 0u;
            }
        }
    }
}

extern "C" void kernel_launch(void* const* d_in, const int* in_sizes, int n_in,
                              void* d_out, int out_size) {
    const float* pts = (const float*)d_in[0];
    float* out = (float*)d_out;
    repulsion_kernel<<<KGRID, KBLOCK>>>(pts, out);
}

// round 16
// speedup vs baseline: 1.5736x; 1.5736x over previous
#include <cuda_runtime.h>
#include <math.h>

// RepulsionLoss: points [4, 8192, 3] f32 -> scalar f32
// R16: two-kernel structure (fusion retired: 3 attempts all lost to barrier/
// fence cost). knn's bound was L1tex wavefronts on scattered per-lane 16B
// gathers (~7 lines per warp-LDG). Fix: per-warp smem staging. Warp ri's 32
// lanes scan overlapping windows of <=2 adjacent flat-contiguous cell rows;
// REDUX min/max gives one span (typ ~50 pts), staged with 2-3 coalesced
// LDG.128, then scanned via LDS.128. Span>96 (z-plane crossing, ~7% of
// blocks) falls back to direct loads -- candidates identical either way.

#define BATCH   4
#define NPTS    8192
#define KNN     8
#define RADIUS  0.07f
#define H2_INV  (1.0f / (0.03f * 0.03f))
#define ALPHA   0.1f

#define GRIDC   18
#define NCELL   (GRIDC * GRIDC * GRIDC)   // 5832

#define CLU     8                         // CTAs per cluster (= per batch)
#define BT      512                       // build threads per block
#define BPPB    (NPTS / CLU)              // 1024 points per build block
#define BPPT    (BPPB / BT)               // 2 points per build thread
#define SLICE   (NCELL / CLU)             // 729 cells per rank
#define SCAN_PT 12                        // 512*12 = 6144 >= 5832

#define QPB     32                        // queries per knn block
#define NROW    9                         // (zz,yy) rows per query (warp = row)
#define KBLOCK  (QPB * NROW)              // 288 threads, 9 warps
#define KGRID   (BATCH * NPTS / QPB)      // 1024 blocks
#define MSTRIDE (NROW * KNN + 1)          // 73: conflict-free columns
#define SCAP    96                        // staged candidates per warp

__device__ int    g_hist[BATCH][NCELL];   // ZERO invariant at launch entry
__device__ int    g_cur [BATCH][NCELL];   // scatter cursors
__device__ int2   g_rr  [BATCH][NCELL];   // per-cell 3-wide x-row range
__device__ float4 g_sorted[BATCH][NPTS];
__device__ float        g_acc;            // zero-init; restored by finalize
__device__ unsigned int g_tick;           // ditto

static __device__ __forceinline__ int cell_coord(float v) {
    int c = (int)(v * (float)GRIDC);
    return c > GRIDC - 1 ? GRIDC - 1 : (c < 0 ? 0 : c);
}

// branch-free sorted insert: independent across k, depth 2
static __device__ __forceinline__ void ins8(float best[KNN], float v) {
#pragma unroll
    for (int k = KNN - 1; k > 0; --k)
        best[k] = fminf(best[k], fmaxf(v, best[k - 1]));
    best[0] = fminf(best[0], v);
}

// bitonic merge of sorted asc m[8] with sorted asc src[8]
static __device__ __forceinline__ void bimerge(float m[KNN], const float* src) {
    float t[KNN];
#pragma unroll
    for (int i = 0; i < KNN; ++i)
        t[i] = fminf(m[i], src[KNN - 1 - i]);
#pragma unroll
    for (int i = 0; i < 4; ++i) {
        const float lo = fminf(t[i], t[i + 4]);
        const float hi = fmaxf(t[i], t[i + 4]);
        t[i] = lo; t[i + 4] = hi;
    }
#pragma unroll
    for (int h = 0; h < 8; h += 4)
#pragma unroll
        for (int i = 0; i < 2; ++i) {
            const float lo = fminf(t[h + i], t[h + i + 2]);
            const float hi = fmaxf(t[h + i], t[h + i + 2]);
            t[h + i] = lo; t[h + i + 2] = hi;
        }
#pragma unroll
    for (int i = 0; i < 8; i += 2) {
        const float lo = fminf(t[i], t[i + 1]);
        const float hi = fmaxf(t[i], t[i + 1]);
        t[i] = lo; t[i + 1] = hi;
    }
#pragma unroll
    for (int i = 0; i < KNN; ++i) m[i] = t[i];
}

static __device__ __forceinline__ void cluster_sync_fenced() {
    __threadfence();
    asm volatile("barrier.cluster.arrive.aligned;" ::: "memory");
    asm volatile("barrier.cluster.wait.aligned;" ::: "memory");
}

// ---- 1: cluster-parallel build (8 CTAs per batch) -----------------------
__global__ __launch_bounds__(BT) __cluster_dims__(CLU, 1, 1)
void build_kernel(const float* __restrict__ pts) {
    __shared__ int s_off[NCELL + 1];
    __shared__ int s_wsum[BT / 32];

    const int b    = blockIdx.x / CLU;
    const int rank = blockIdx.x % CLU;
    const int tid  = threadIdx.x;
    const int lane = tid & 31;
    const int warp = tid >> 5;
    const float* __restrict__ base = pts + (size_t)b * NPTS * 3;

    float px[BPPT], py[BPPT], pz[BPPT];
    int   pc[BPPT];
#pragma unroll
    for (int r = 0; r < BPPT; ++r) {
        const int i = rank * BPPB + r * BT + tid;
        px[r] = __ldg(base + 3 * i + 0);
        py[r] = __ldg(base + 3 * i + 1);
        pz[r] = __ldg(base + 3 * i + 2);
        pc[r] = (cell_coord(pz[r]) * GRIDC + cell_coord(py[r])) * GRIDC
                + cell_coord(px[r]);
        atomicAdd(&g_hist[b][pc[r]], 1);
    }
    cluster_sync_fenced();

    {
        const int i0 = tid * SCAN_PT;
        int v[SCAN_PT];
        int sum = 0;
#pragma unroll
        for (int r = 0; r < SCAN_PT; ++r) {
            const int i = i0 + r;
            v[r] = (i < NCELL) ? g_hist[b][i] : 0;
            sum += v[r];
        }
        int inc = sum;
#pragma unroll
        for (int off = 1; off < 32; off <<= 1) {
            const int n = __shfl_up_sync(0xffffffffu, inc, off);
            if (lane >= off) inc += n;
        }
        if (lane == 31) s_wsum[warp] = inc;
        __syncthreads();
        int wbase = 0;
        for (int w = 0; w < warp; ++w) wbase += s_wsum[w];
        int run = wbase + inc - sum;
#pragma unroll
        for (int r = 0; r < SCAN_PT; ++r) {
            const int i = i0 + r;
            if (i < NCELL) s_off[i] = run;
            run += v[r];
        }
        if (tid == 0) s_off[NCELL] = NPTS;
        __syncthreads();

        for (int i = rank * SLICE + tid; i < rank * SLICE + SLICE; i += BT) {
            g_cur[b][i] = s_off[i];
            const int x  = i % GRIDC;
            const int rb = i - x;
            const int xs = s_off[rb + (x > 0 ? x - 1 : 0)];
            const int xe = s_off[rb + (x < GRIDC - 1 ? x + 1 : GRIDC - 1) + 1];
            g_rr[b][i] = make_int2(xs, xe);
        }
    }
    cluster_sync_fenced();

    for (int i = rank * SLICE + tid; i < rank * SLICE + SLICE; i += BT)
        g_hist[b][i] = 0;
#pragma unroll
    for (int r = 0; r < BPPT; ++r) {
        const int pos = atomicAdd(&g_cur[b][pc[r]], 1);
        g_sorted[b][pos] = make_float4(px[r], py[r], pz[r], 0.0f);
    }
}

// ---- 2: fused grid-KNN + loss (staged gathers, parallel merge) ----------
__global__ __launch_bounds__(KBLOCK, 7) void knn_kernel(float* __restrict__ out) {
    __shared__ float4 s_stage[NROW][SCAP];          // 13.8 KB
    __shared__ float  s_m[QPB][MSTRIDE];            // 9.3 KB

    const int tid    = threadIdx.x;
    const int ri     = tid >> 5;
    const int qlocal = tid & 31;

    const int blocks_per_batch = NPTS / QPB;        // 256
    const int b  = blockIdx.x / blocks_per_batch;
    const int qi = (blockIdx.x % blocks_per_batch) * QPB + qlocal;

    const float4 p = __ldg(&g_sorted[b][qi]);
    const float qx = p.x, qy = p.y, qz = p.z;
    const int cx = cell_coord(qx);
    const int cy = cell_coord(qy);
    const int cz = cell_coord(qz);

    float best[KNN];
#pragma unroll
    for (int k = 0; k < KNN; ++k) best[k] = 3.0e38f;

    const int zz = cz - 1 + ri / 3;
    const int yy = cy - 1 + ri % 3;
    const bool valid = ((unsigned)zz < GRIDC) && ((unsigned)yy < GRIDC);

    int js = 0x7fffffff, je = 0;   // reduce identities for invalid lanes
    if (valid) {
        const int2 r = __ldg(&g_rr[b][(zz * GRIDC + yy) * GRIDC + cx]);
        js = r.x; je = r.y;
    }

    const int wbase = __reduce_min_sync(0xffffffffu, js);
    const int wend  = __reduce_max_sync(0xffffffffu, je);
    const int n     = wend - wbase;

    if (n > 0 && n <= SCAP) {
        // cooperative coalesced staging of the warp's union span
        for (int i = qlocal; i < n; i += 32)
            s_stage[ri][i] = __ldg(&g_sorted[b][wbase + i]);
        __syncwarp();
        for (int j = js; j < je; ++j) {
            const float4 c = s_stage[ri][j - wbase];
            const float dx = qx - c.x;
            const float dy = qy - c.y;
            const float dz = qz - c.z;
            const float d2 = fmaf(dx, dx, fmaf(dy, dy, dz * dz));
            ins8(best, d2);
        }
    } else if (wend > 0) {
        // rare fallback (z-plane crossing): direct gathers, same candidates
        for (int j = js; j < je; ++j) {
            const float4 c = __ldg(&g_sorted[b][j]);
            const float dx = qx - c.x;
            const float dy = qy - c.y;
            const float dz = qz - c.z;
            const float d2 = fmaf(dx, dx, fmaf(dy, dy, dz * dz));
            ins8(best, d2);
        }
    }

#pragma unroll
    for (int k = 0; k < KNN; ++k) s_m[qlocal][ri * KNN + k] = best[k];
    __syncthreads();

    // merge tree: warp0 <- lists 1..3, warp4 <- lists 5..8 (parallel)
    float m[KNN];
    if (ri == 0 || ri == 4) {
#pragma unroll
        for (int k = 0; k < KNN; ++k) m[k] = best[k];
        const int first = (ri == 0) ? 1 : 5;
        const int last  = (ri == 0) ? 3 : 8;
        for (int r = first; r <= last; ++r)
            bimerge(m, &s_m[qlocal][r * KNN]);
        if (ri == 4) {
#pragma unroll
            for (int k = 0; k < KNN; ++k) s_m[qlocal][4 * KNN + k] = m[k];
        }
    }
    __syncthreads();

    if (ri == 0) {
        bimerge(m, &s_m[qlocal][4 * KNN]);

        // unfilled slots (3e38) -> exp underflows to 0 -> contribute nothing
        float s = 0.0f;
#pragma unroll
        for (int k = 0; k < KNN; ++k) {
            const float d2 = m[k];
            const float dn = sqrtf(fmaxf(d2, 1e-12f));
            const float w  = __expf(-d2 * H2_INV);
            s = fmaf(RADIUS - dn, w, s);
        }
#pragma unroll
        for (int off = 16; off > 0; off >>= 1)
            s += __shfl_xor_sync(0xffffffffu, s, off);

        if (qlocal == 0) {
            atomicAdd(&g_acc, s);
            __threadfence();
            const unsigned t = atomicAdd(&g_tick, 1u);
            if (t == KGRID - 1) {
                __threadfence();
                const float total = atomicAdd(&g_acc, 0.0f);
                out[0] = ALPHA * total * (1.0f / (float)(BATCH * NPTS * KNN));
                g_acc = 0.0f;                   // restore for graph replay
                __threadfence();
                g_tick = 0u;
            }
        }
    }
}

extern "C" void kernel_launch(void* const* d_in, const int* in_sizes, int n_in,
                              void* d_out, int out_size) {
    const float* pts = (const float*)d_in[0];
    float* out = (float*)d_out;

    build_kernel<<<BATCH * CLU, BT>>>(pts);
    knn_kernel  <<<KGRID, KBLOCK>>>(out);
}

// round 17
// speedup vs baseline: 1.9195x; 1.2198x over previous
#include <cuda_runtime.h>
#include <math.h>

// RepulsionLoss: points [4, 8192, 3] f32 -> scalar f32
// R17: best-of-breed recombination + PDL overlap.
//  - GRIDC=16 (R13: measured rel_err 0.0, power-of-2 cell math)
//  - cluster-parallel build (R13)
//  - knn: 9-way row split, branch-free ins8, parallel bitonic merge tree (R14)
//  - NEW: programmatic dependent launch -- knn is launched with
//    ProgrammaticStreamSerialization and begins with
//    cudaGridDependencySynchronize(); build triggers early launch
//    completion. knn's launch setup overlaps build execution, recovering
//    most of the second kernel's launch envelope.

#define BATCH   4
#define NPTS    8192
#define KNN     8
#define RADIUS  0.07f
#define H2_INV  (1.0f / (0.03f * 0.03f))
#define ALPHA   0.1f

#define GRIDC   16
#define NCELL   (GRIDC * GRIDC * GRIDC)   // 4096

#define CLU     8                         // CTAs per cluster (= per batch)
#define BT      512                       // build threads per block
#define BPPB    (NPTS / CLU)              // 1024 points per build block
#define BPPT    (BPPB / BT)               // 2 points per build thread
#define SLICE   (NCELL / CLU)             // 512 cells per rank
#define SCAN_PT 8                         // 512*8 = 4096 exact

#define QPB     32                        // queries per knn block
#define NROW    9                         // (zz,yy) rows per query (warp = row)
#define KBLOCK  (QPB * NROW)              // 288 threads, 9 warps
#define KGRID   (BATCH * NPTS / QPB)      // 1024 blocks
#define MSTRIDE (NROW * KNN + 1)          // 73: conflict-free columns

__device__ int    g_hist[BATCH][NCELL];   // ZERO invariant at launch entry
__device__ int    g_cur [BATCH][NCELL];   // scatter cursors
__device__ int2   g_rr  [BATCH][NCELL];   // per-cell 3-wide x-row range
__device__ float4 g_sorted[BATCH][NPTS];
__device__ float        g_acc;            // zero-init; restored by finalize
__device__ unsigned int g_tick;           // ditto

static __device__ __forceinline__ int cell_coord(float v) {
    int c = (int)(v * (float)GRIDC);
    return c > GRIDC - 1 ? GRIDC - 1 : (c < 0 ? 0 : c);
}

// branch-free sorted insert: independent across k, depth 2
static __device__ __forceinline__ void ins8(float best[KNN], float v) {
#pragma unroll
    for (int k = KNN - 1; k > 0; --k)
        best[k] = fminf(best[k], fmaxf(v, best[k - 1]));
    best[0] = fminf(best[0], v);
}

// bitonic merge of sorted asc m[8] with sorted asc src[8]
static __device__ __forceinline__ void bimerge(float m[KNN], const float* src) {
    float t[KNN];
#pragma unroll
    for (int i = 0; i < KNN; ++i)
        t[i] = fminf(m[i], src[KNN - 1 - i]);
#pragma unroll
    for (int i = 0; i < 4; ++i) {
        const float lo = fminf(t[i], t[i + 4]);
        const float hi = fmaxf(t[i], t[i + 4]);
        t[i] = lo; t[i + 4] = hi;
    }
#pragma unroll
    for (int h = 0; h < 8; h += 4)
#pragma unroll
        for (int i = 0; i < 2; ++i) {
            const float lo = fminf(t[h + i], t[h + i + 2]);
            const float hi = fmaxf(t[h + i], t[h + i + 2]);
            t[h + i] = lo; t[h + i + 2] = hi;
        }
#pragma unroll
    for (int i = 0; i < 8; i += 2) {
        const float lo = fminf(t[i], t[i + 1]);
        const float hi = fmaxf(t[i], t[i + 1]);
        t[i] = lo; t[i + 1] = hi;
    }
#pragma unroll
    for (int i = 0; i < KNN; ++i) m[i] = t[i];
}

static __device__ __forceinline__ void cluster_sync_fenced() {
    __threadfence();
    asm volatile("barrier.cluster.arrive.aligned;" ::: "memory");
    asm volatile("barrier.cluster.wait.aligned;" ::: "memory");
}

// ---- 1: cluster-parallel build (8 CTAs per batch) -----------------------
__global__ __launch_bounds__(BT) __cluster_dims__(CLU, 1, 1)
void build_kernel(const float* __restrict__ pts) {
    __shared__ int s_off[NCELL + 1];
    __shared__ int s_wsum[BT / 32];

    const int b    = blockIdx.x / CLU;
    const int rank = blockIdx.x % CLU;
    const int tid  = threadIdx.x;
    const int lane = tid & 31;
    const int warp = tid >> 5;
    const float* __restrict__ base = pts + (size_t)b * NPTS * 3;

    // Phase 1: histogram via global atomics; coords stay in registers
    float px[BPPT], py[BPPT], pz[BPPT];
    int   pc[BPPT];
#pragma unroll
    for (int r = 0; r < BPPT; ++r) {
        const int i = rank * BPPB + r * BT + tid;
        px[r] = __ldg(base + 3 * i + 0);
        py[r] = __ldg(base + 3 * i + 1);
        pz[r] = __ldg(base + 3 * i + 2);
        pc[r] = (cell_coord(pz[r]) * GRIDC + cell_coord(py[r])) * GRIDC
                + cell_coord(px[r]);
        atomicAdd(&g_hist[b][pc[r]], 1);
    }
    cluster_sync_fenced();

    // Phase 2: redundant full scan in own smem; write own slice
    {
        const int i0 = tid * SCAN_PT;
        int v[SCAN_PT];
        int sum = 0;
#pragma unroll
        for (int r = 0; r < SCAN_PT; ++r) {
            v[r] = g_hist[b][i0 + r];
            sum += v[r];
        }
        int inc = sum;
#pragma unroll
        for (int off = 1; off < 32; off <<= 1) {
            const int n = __shfl_up_sync(0xffffffffu, inc, off);
            if (lane >= off) inc += n;
        }
        if (lane == 31) s_wsum[warp] = inc;
        __syncthreads();
        int wbase = 0;
        for (int w = 0; w < warp; ++w) wbase += s_wsum[w];
        int run = wbase + inc - sum;
#pragma unroll
        for (int r = 0; r < SCAN_PT; ++r) {
            s_off[i0 + r] = run;
            run += v[r];
        }
        if (tid == BT - 1) s_off[NCELL] = NPTS;   // sentinel
        __syncthreads();

        // own 512-cell slice: cursors + 3-wide x-row ranges
        const int i = rank * SLICE + tid;          // SLICE == BT
        g_cur[b][i] = s_off[i];
        const int x  = i & (GRIDC - 1);
        const int rb = i - x;
        const int xs = s_off[rb + (x > 0 ? x - 1 : 0)];
        const int xe = s_off[rb + (x < GRIDC - 1 ? x + 1 : GRIDC - 1) + 1];
        g_rr[b][i] = make_int2(xs, xe);
    }
    cluster_sync_fenced();

    // Phase 3: restore g_hist zero-invariant + scatter
    g_hist[b][rank * SLICE + tid] = 0;
#pragma unroll
    for (int r = 0; r < BPPT; ++r) {
        const int pos = atomicAdd(&g_cur[b][pc[r]], 1);
        g_sorted[b][pos] = make_float4(px[r], py[r], pz[r], 0.0f);
    }

    // allow the dependent knn grid to begin launching (PDL)
    cudaTriggerProgrammaticLaunchCompletion();
}

// ---- 2: fused grid-KNN + loss (9 rows/query, parallel merge tree) -------
__global__ __launch_bounds__(KBLOCK, 7) void knn_kernel(float* __restrict__ out) {
    // PDL: wait until build's memory is visible before touching its outputs
    cudaGridDependencySynchronize();

    __shared__ float s_m[QPB][MSTRIDE];

    const int tid    = threadIdx.x;
    const int ri     = tid >> 5;          // row index 0..8 (= warp id)
    const int qlocal = tid & 31;          // lane = local query

    const int blocks_per_batch = NPTS / QPB;           // 256
    const int b  = blockIdx.x / blocks_per_batch;
    const int qi = (blockIdx.x % blocks_per_batch) * QPB + qlocal;

    const float4 p = __ldg(&g_sorted[b][qi]);
    const float qx = p.x, qy = p.y, qz = p.z;
    const int cx = cell_coord(qx);
    const int cy = cell_coord(qy);
    const int cz = cell_coord(qz);

    float best[KNN];                      // sorted ascending
#pragma unroll
    for (int k = 0; k < KNN; ++k) best[k] = 3.0e38f;

    const int zz = cz - 1 + ri / 3;
    const int yy = cy - 1 + ri % 3;
    if ((unsigned)zz < GRIDC && (unsigned)yy < GRIDC) {
        const int2 r = __ldg(&g_rr[b][(zz * GRIDC + yy) * GRIDC + cx]);
#pragma unroll 4
        for (int j = r.x; j < r.y; ++j) {
            const float4 c = __ldg(&g_sorted[b][j]);
            const float dx = qx - c.x;
            const float dy = qy - c.y;
            const float dz = qz - c.z;
            const float d2 = fmaf(dx, dx, fmaf(dy, dy, dz * dz));
            ins8(best, d2);               // unconditional, depth-2
        }
    }

    // publish row partials (stride-73 rows: conflict-free)
#pragma unroll
    for (int k = 0; k < KNN; ++k) s_m[qlocal][ri * KNN + k] = best[k];
    __syncthreads();

    // merge tree: warp0 <- lists 1..3, warp4 <- lists 5..8 (parallel)
    float m[KNN];
    if (ri == 0 || ri == 4) {
#pragma unroll
        for (int k = 0; k < KNN; ++k) m[k] = best[k];   // own row (sorted)
        const int first = (ri == 0) ? 1 : 5;
        const int last  = (ri == 0) ? 3 : 8;
        for (int r = first; r <= last; ++r)
            bimerge(m, &s_m[qlocal][r * KNN]);
        if (ri == 4) {
#pragma unroll
            for (int k = 0; k < KNN; ++k) s_m[qlocal][4 * KNN + k] = m[k];
        }
    }
    __syncthreads();

    if (ri == 0) {                        // final merge + loss
        bimerge(m, &s_m[qlocal][4 * KNN]);

        // unfilled slots (3e38) -> exp underflows to 0 -> contribute nothing
        float s = 0.0f;
#pragma unroll
        for (int k = 0; k < KNN; ++k) {
            const float d2 = m[k];
            const float dn = sqrtf(fmaxf(d2, 1e-12f));
            const float w  = __expf(-d2 * H2_INV);
            s = fmaf(RADIUS - dn, w, s);
        }
#pragma unroll
        for (int off = 16; off > 0; off >>= 1)
            s += __shfl_xor_sync(0xffffffffu, s, off);

        if (qlocal == 0) {
            atomicAdd(&g_acc, s);
            __threadfence();
            const unsigned t = atomicAdd(&g_tick, 1u);
            if (t == KGRID - 1) {              // last block finalizes
                __threadfence();
                const float total = atomicAdd(&g_acc, 0.0f);
                out[0] = ALPHA * total * (1.0f / (float)(BATCH * NPTS * KNN));
                g_acc = 0.0f;                   // restore for graph replay
                __threadfence();
                g_tick = 0u;
            }
        }
    }
}

extern "C" void kernel_launch(void* const* d_in, const int* in_sizes, int n_in,
                              void* d_out, int out_size) {
    const float* pts = (const float*)d_in[0];
    float* out = (float*)d_out;

    build_kernel<<<BATCH * CLU, BT>>>(pts);

    // knn with programmatic dependent launch: its grid setup overlaps build
    cudaLaunchConfig_t cfg = {};
    cfg.gridDim  = dim3(KGRID, 1, 1);
    cfg.blockDim = dim3(KBLOCK, 1, 1);
    cudaLaunchAttribute attrs[1];
    attrs[0].id = cudaLaunchAttributeProgrammaticStreamSerialization;
    attrs[0].val.programmaticStreamSerializationAllowed = 1;
    cfg.attrs    = attrs;
    cfg.numAttrs = 1;
    cudaLaunchKernelEx(&cfg, knn_kernel, out);
}